// round 14
// baseline (speedup 1.0000x reference)
#include <cuda_runtime.h>

#define NTOT      40
#define NX        20
#define BATCHN    524288
#define TPB       320                 // 32 rows * 10 float4-chunks per row
#define ROWS_TILE 32
#define ITERS     4
#define ROWS_BLOCK (ROWS_TILE * ITERS)       // 128 rows per block
#define NBLOCKS   (BATCHN / ROWS_BLOCK)      // 4096

#define NGRP      64                  // 64 groups x 64 blocks
#define GRP_SHIFT 6

// Per-block double partials (each block writes its own slot every launch).
__device__ double g_part_dd[NBLOCKS];
__device__ double g_part_pi[NBLOCKS];
// Spread tickets: 256B stride defeats L2 same-address atomic serialization
// (the common factor in every failed fused variant: 4096 same-address atomics
// arrive in ~888-block wave bursts; at ~32cyc/op the queue never drains and
// CTAs hold SM slots waiting -> next wave starves -> the ~17us fused penalty).
__device__ unsigned int g_tick[NGRP][64];   // use [g][0]; 256B apart
__device__ unsigned int g_super;            // 64 ops total — negligible

__device__ __forceinline__ unsigned int atomRelease(unsigned int* p)
{
    unsigned int old;
    asm volatile("atom.release.gpu.global.add.u32 %0, [%1], %2;"
                 : "=r"(old) : "l"(p), "r"(1u) : "memory");
    return old;
}

__device__ __forceinline__ void fenceAcqRelGpu()
{
    asm volatile("fence.acq_rel.gpu;" ::: "memory");
}

__global__ __launch_bounds__(TPB) void hybrid_loss_kernel(
    const float* __restrict__ pred,
    const float* __restrict__ targ,
    const float* __restrict__ ycur,
    float* __restrict__ out)
{
    __shared__ __align__(16) float sp[ROWS_TILE][44];   // 44-stride pad, 16B rows

    const int t = threadIdx.x;
    const int r = t / 10;           // row within tile (0..31)
    const int j = t - r * 10;       // float4 chunk within row (0..9)

    const float4* __restrict__ p4 = (const float4*)pred;
    const float4* __restrict__ y4 = (const float4*)ycur;
    const float2* __restrict__ t2 = (const float2*)targ;

    const int base_row = blockIdx.x * ROWS_BLOCK;

    float acc_dd = 0.0f;
    float acc_pi = 0.0f;

    // Prefetch iteration 0 (pred/y coalesced float4; targ float2 over observed cols)
    float4 pv = p4[base_row * 10 + t];
    float4 yv = y4[base_row * 10 + t];
    float2 tv = t2[(base_row + r) * 20 + j];

    // Stencil neighbor indices within the 40-wide row (periodic wrap).
    const int i0  = 4 * j;
    const int im2 = (j == 0) ? 38 : i0 - 2;
    const int im1 = (j == 0) ? 39 : i0 - 1;
    const int ip1 = (j == 9) ? 0  : i0 + 4;

    #pragma unroll
    for (int it = 0; it < ITERS; ++it) {
        float4 pc = pv;
        float4 yc = yv;
        float2 tc = tv;

        // Prefetch next tile before the barrier — LDG latency overlaps barrier+compute.
        if (it + 1 < ITERS) {
            int nb = base_row + (it + 1) * ROWS_TILE;
            pv = p4[nb * 10 + t];
            yv = y4[nb * 10 + t];
            tv = t2[(nb + r) * 20 + j];
        }

        // Stage pred tile (float4 store: row stride 176B, 16B aligned).
        *reinterpret_cast<float4*>(&sp[r][i0]) = pc;
        __syncthreads();

        // ---- data-driven term: elements 2j, 2j+1 of row r (cols 0..19) ----
        {
            float d0 = sp[r][2 * j]     - tc.x;
            float d1 = sp[r][2 * j + 1] - tc.y;
            acc_dd += d0 * d0 + d1 * d1;
        }

        // ---- physics term: Lorenz-96 RHS with periodic wrap ----
        {
            float pm2 = sp[r][im2];
            float pm1 = sp[r][im1];
            float pp1 = sp[r][ip1];
            float p0 = pc.x, p1 = pc.y, p2 = pc.z, p3 = pc.w;

            float f0 = (p1  - pm2) * pm1 - p0 + 8.0f;
            float f1 = (p2  - pm1) * p0  - p1 + 8.0f;
            float f2 = (p3  - p0 ) * p1  - p2 + 8.0f;
            float f3 = (pp1 - p1 ) * p2  - p3 + 8.0f;

            float d0 = (p0 - yc.x) * 100.0f - f0;
            float d1 = (p1 - yc.y) * 100.0f - f1;
            float d2 = (p2 - yc.z) * 100.0f - f2;
            float d3 = (p3 - yc.w) * 100.0f - f3;

            acc_pi += d0 * d0 + d1 * d1 + d2 * d2 + d3 * d3;
        }
        __syncthreads();   // protect smem before next iteration's store
    }

    // ---- block reduction: warp shuffle (float) -> smem (double) ----
    #pragma unroll
    for (int o = 16; o; o >>= 1) {
        acc_dd += __shfl_xor_sync(0xFFFFFFFFu, acc_dd, o);
        acc_pi += __shfl_xor_sync(0xFFFFFFFFu, acc_pi, o);
    }
    __shared__ double wdd[TPB / 32], wpi[TPB / 32];
    __shared__ int s_last;
    const int lane = t & 31, w = t >> 5;
    if (lane == 0) { wdd[w] = (double)acc_dd; wpi[w] = (double)acc_pi; }
    __syncthreads();
    if (t == 0) {
        double a = 0.0, b = 0.0;
        #pragma unroll
        for (int i = 0; i < TPB / 32; ++i) { a += wdd[i]; b += wpi[i]; }
        const int bid = blockIdx.x;
        g_part_dd[bid] = a;
        g_part_pi[bid] = b;
        // Level 1: release-add on this block's group counter (64 contenders,
        // 256B-strided addresses -> parallel across L2 slices).
        int last = 0;
        unsigned int v = atomRelease(&g_tick[bid >> GRP_SHIFT][0]);
        if (v == (unsigned int)((NBLOCKS >> GRP_SHIFT) - 1)) {
            // Level 2: group winner escalates (64 ops total on one address).
            unsigned int s = atomRelease(&g_super);
            last = (s == NGRP - 1);
        }
        s_last = last;
    }
    __syncthreads();

    // ---- global-last block only: one acquire fence, fixed-order final reduce ----
    if (s_last) {
        if (t == 0) fenceAcqRelGpu();   // single L1 invalidate, one SM, once
        __syncthreads();
        double a = 0.0, b = 0.0;
        for (int k = t; k < NBLOCKS; k += TPB) {
            a += __ldcg(&g_part_dd[k]);   // L2 path
            b += __ldcg(&g_part_pi[k]);
        }
        #pragma unroll
        for (int o = 16; o; o >>= 1) {
            a += __shfl_xor_sync(0xFFFFFFFFu, a, o);
            b += __shfl_xor_sync(0xFFFFFFFFu, b, o);
        }
        if (lane == 0) { wdd[w] = a; wpi[w] = b; }
        __syncthreads();
        if (t == 0) {
            double A = 0.0, B = 0.0;
            #pragma unroll
            for (int i = 0; i < TPB / 32; ++i) { A += wdd[i]; B += wpi[i]; }
            double l_dd = A / ((double)BATCHN * (double)NX);
            double l_pi = B / ((double)BATCHN * (double)NTOT);
            out[0] = (float)(l_dd + 0.1 * l_pi);   // total_loss
            out[1] = (float)l_dd;
            out[2] = (float)l_pi;
        }
        // Re-arm all counters for the next graph replay (end-of-kernel
        // implicit fence makes these visible before any later launch).
        if (t < NGRP) g_tick[t][0] = 0;
        if (t == 0)   g_super = 0;
    }
}

extern "C" void kernel_launch(void* const* d_in, const int* in_sizes, int n_in,
                              void* d_out, int out_size)
{
    const float* pred = (const float*)d_in[0];   // predictions [524288, 40]
    const float* targ = (const float*)d_in[1];   // targets     [524288, 40]
    const float* ycur = (const float*)d_in[2];   // y_current   [524288, 40]
    float* out = (float*)d_out;                  // [total, l_dd, l_pi]

    hybrid_loss_kernel<<<NBLOCKS, TPB>>>(pred, targ, ycur, out);
}

// round 15
// speedup vs baseline: 1.1861x; 1.1861x over previous
#include <cuda_runtime.h>

#define NTOT      40
#define NX        20
#define BATCHN    524288
#define TPB       320                 // 32 rows * 10 float4-chunks per row
#define ROWS_TILE 32
#define ITERS     4
#define ROWS_BLOCK (ROWS_TILE * ITERS)       // 128 rows per block
#define NBLOCKS   (BATCHN / ROWS_BLOCK)      // 4096

__global__ __launch_bounds__(TPB) void hybrid_loss_kernel(
    const float* __restrict__ pred,
    const float* __restrict__ targ,
    const float* __restrict__ ycur,
    float* __restrict__ out)
{
    __shared__ __align__(16) float sp[ROWS_TILE][44];   // 44-stride pad, 16B rows

    const int t = threadIdx.x;
    const int r = t / 10;           // row within tile (0..31)
    const int j = t - r * 10;       // float4 chunk within row (0..9)

    const float4* __restrict__ p4 = (const float4*)pred;
    const float4* __restrict__ y4 = (const float4*)ycur;
    const float2* __restrict__ t2 = (const float2*)targ;

    const int base_row = blockIdx.x * ROWS_BLOCK;

    float acc_dd = 0.0f;
    float acc_pi = 0.0f;

    // Prefetch iteration 0 (pred/y coalesced float4; targ float2 over observed cols)
    float4 pv = p4[base_row * 10 + t];
    float4 yv = y4[base_row * 10 + t];
    float2 tv = t2[(base_row + r) * 20 + j];

    // Stencil neighbor indices within the 40-wide row (periodic wrap).
    const int i0  = 4 * j;
    const int im2 = (j == 0) ? 38 : i0 - 2;
    const int im1 = (j == 0) ? 39 : i0 - 1;
    const int ip1 = (j == 9) ? 0  : i0 + 4;

    #pragma unroll
    for (int it = 0; it < ITERS; ++it) {
        float4 pc = pv;
        float4 yc = yv;
        float2 tc = tv;

        // Prefetch next tile before the barrier — LDG latency overlaps barrier+compute.
        if (it + 1 < ITERS) {
            int nb = base_row + (it + 1) * ROWS_TILE;
            pv = p4[nb * 10 + t];
            yv = y4[nb * 10 + t];
            tv = t2[(nb + r) * 20 + j];
        }

        // Stage pred tile (float4 store: row stride 176B, 16B aligned).
        *reinterpret_cast<float4*>(&sp[r][i0]) = pc;
        __syncthreads();

        // ---- data-driven term: elements 2j, 2j+1 of row r (cols 0..19) ----
        {
            float d0 = sp[r][2 * j]     - tc.x;
            float d1 = sp[r][2 * j + 1] - tc.y;
            acc_dd += d0 * d0 + d1 * d1;
        }

        // ---- physics term: Lorenz-96 RHS with periodic wrap ----
        {
            float pm2 = sp[r][im2];
            float pm1 = sp[r][im1];
            float pp1 = sp[r][ip1];
            float p0 = pc.x, p1 = pc.y, p2 = pc.z, p3 = pc.w;

            float f0 = (p1  - pm2) * pm1 - p0 + 8.0f;
            float f1 = (p2  - pm1) * p0  - p1 + 8.0f;
            float f2 = (p3  - p0 ) * p1  - p2 + 8.0f;
            float f3 = (pp1 - p1 ) * p2  - p3 + 8.0f;

            float d0 = (p0 - yc.x) * 100.0f - f0;
            float d1 = (p1 - yc.y) * 100.0f - f1;
            float d2 = (p2 - yc.z) * 100.0f - f2;
            float d3 = (p3 - yc.w) * 100.0f - f3;

            acc_pi += d0 * d0 + d1 * d1 + d2 * d2 + d3 * d3;
        }
        __syncthreads();   // protect smem before next iteration's store
    }

    // ---- block reduction: warp shuffle (float) -> smem (double) ----
    #pragma unroll
    for (int o = 16; o; o >>= 1) {
        acc_dd += __shfl_xor_sync(0xFFFFFFFFu, acc_dd, o);
        acc_pi += __shfl_xor_sync(0xFFFFFFFFu, acc_pi, o);
    }
    __shared__ double wdd[TPB / 32], wpi[TPB / 32];
    const int lane = t & 31, w = t >> 5;
    if (lane == 0) { wdd[w] = (double)acc_dd; wpi[w] = (double)acc_pi; }
    __syncthreads();

    // ---- fire-and-forget: 3 scaled RED.ADD.F32 into d_out, no waiting ----
    // atomicAdd with unused result compiles to RED (no return trip): the block
    // retires immediately. d_out is zeroed each replay by a memset graph node.
    // Float accumulation of 4096 ~equal terms: rel err ~1e-6 << 1e-3 threshold.
    if (t == 0) {
        double a = 0.0, b = 0.0;
        #pragma unroll
        for (int i = 0; i < TPB / 32; ++i) { a += wdd[i]; b += wpi[i]; }
        double s_dd = a / ((double)BATCHN * (double)NX);
        double s_pi = b / ((double)BATCHN * (double)NTOT);
        atomicAdd(&out[0], (float)(s_dd + 0.1 * s_pi));   // total_loss
        atomicAdd(&out[1], (float)s_dd);                  // l_dd
        atomicAdd(&out[2], (float)s_pi);                  // l_pi
    }
}

extern "C" void kernel_launch(void* const* d_in, const int* in_sizes, int n_in,
                              void* d_out, int out_size)
{
    const float* pred = (const float*)d_in[0];   // predictions [524288, 40]
    const float* targ = (const float*)d_in[1];   // targets     [524288, 40]
    const float* ycur = (const float*)d_in[2];   // y_current   [524288, 40]
    float* out = (float*)d_out;                  // [total, l_dd, l_pi]

    // Zero the (poisoned) output each invocation; capturable memset node.
    cudaMemsetAsync(d_out, 0, (size_t)out_size * sizeof(float), 0);
    hybrid_loss_kernel<<<NBLOCKS, TPB>>>(pred, targ, ycur, out);
}

// round 16
// speedup vs baseline: 1.2794x; 1.0786x over previous
#include <cuda_runtime.h>

#define NTOT      40
#define NX        20
#define BATCHN    524288
#define TPB       320                 // 32 rows * 10 float4-chunks per row
#define ROWS_TILE 32
#define NTILES    (BATCHN / ROWS_TILE)   // 16384
#define GRID      1480                // 148 SMs x 10 CTAs; RED count 4096->1480

__global__ __launch_bounds__(TPB) void hybrid_loss_kernel(
    const float* __restrict__ pred,
    const float* __restrict__ targ,
    const float* __restrict__ ycur,
    float* __restrict__ out)
{
    __shared__ __align__(16) float sp[ROWS_TILE][44];   // 44-stride pad, 16B rows

    const int t = threadIdx.x;
    const int r = t / 10;           // row within tile (0..31)
    const int j = t - r * 10;       // float4 chunk within row (0..9)

    const float4* __restrict__ p4 = (const float4*)pred;
    const float4* __restrict__ y4 = (const float4*)ycur;
    const float2* __restrict__ t2 = (const float2*)targ;

    float acc_dd = 0.0f;
    float acc_pi = 0.0f;

    // Stencil neighbor indices within the 40-wide row (periodic wrap).
    const int i0  = 4 * j;
    const int im2 = (j == 0) ? 38 : i0 - 2;
    const int im1 = (j == 0) ? 39 : i0 - 1;
    const int ip1 = (j == 9) ? 0  : i0 + 4;

    // Grid-stride over 32-row tiles; trip count uniform across the block
    // (depends only on blockIdx) so the barriers below are safe.
    int tile = blockIdx.x;
    {
        const int b0 = tile * ROWS_TILE;
        // Prefetch first tile (pred/y coalesced float4; targ float2, observed cols).
        float4 pv = p4[b0 * 10 + t];
        float4 yv = y4[b0 * 10 + t];
        float2 tv = t2[(b0 + r) * 20 + j];

        while (tile < NTILES) {
            float4 pc = pv;
            float4 yc = yv;
            float2 tc = tv;

            // Prefetch next strided tile before the barrier.
            const int nt = tile + GRID;
            if (nt < NTILES) {
                const int nb = nt * ROWS_TILE;
                pv = p4[nb * 10 + t];
                yv = y4[nb * 10 + t];
                tv = t2[(nb + r) * 20 + j];
            }

            // Stage pred tile (float4 store: row stride 176B, 16B aligned).
            *reinterpret_cast<float4*>(&sp[r][i0]) = pc;
            __syncthreads();

            // ---- data-driven term: elements 2j, 2j+1 of row r (cols 0..19) ----
            {
                float d0 = sp[r][2 * j]     - tc.x;
                float d1 = sp[r][2 * j + 1] - tc.y;
                acc_dd += d0 * d0 + d1 * d1;
            }

            // ---- physics term: Lorenz-96 RHS with periodic wrap ----
            {
                float pm2 = sp[r][im2];
                float pm1 = sp[r][im1];
                float pp1 = sp[r][ip1];
                float p0 = pc.x, p1 = pc.y, p2 = pc.z, p3 = pc.w;

                float f0 = (p1  - pm2) * pm1 - p0 + 8.0f;
                float f1 = (p2  - pm1) * p0  - p1 + 8.0f;
                float f2 = (p3  - p0 ) * p1  - p2 + 8.0f;
                float f3 = (pp1 - p1 ) * p2  - p3 + 8.0f;

                float d0 = (p0 - yc.x) * 100.0f - f0;
                float d1 = (p1 - yc.y) * 100.0f - f1;
                float d2 = (p2 - yc.z) * 100.0f - f2;
                float d3 = (p3 - yc.w) * 100.0f - f3;

                acc_pi += d0 * d0 + d1 * d1 + d2 * d2 + d3 * d3;
            }
            __syncthreads();   // protect smem before next iteration's store
            tile = nt;
        }
    }

    // ---- block reduction: warp shuffle (float) -> smem (double) ----
    #pragma unroll
    for (int o = 16; o; o >>= 1) {
        acc_dd += __shfl_xor_sync(0xFFFFFFFFu, acc_dd, o);
        acc_pi += __shfl_xor_sync(0xFFFFFFFFu, acc_pi, o);
    }
    __shared__ double wdd[TPB / 32], wpi[TPB / 32];
    const int lane = t & 31, w = t >> 5;
    if (lane == 0) { wdd[w] = (double)acc_dd; wpi[w] = (double)acc_pi; }
    __syncthreads();

    // ---- fire-and-forget: 3 scaled RED.ADD.F32 into d_out, no waiting ----
    // atomicAdd with unused result compiles to RED (no return trip): block
    // retires immediately. 1480 blocks x 3 ops ~= 1.3us L2 drain, overlapped.
    // d_out is zeroed each replay by the memset graph node below.
    if (t == 0) {
        double a = 0.0, b = 0.0;
        #pragma unroll
        for (int i = 0; i < TPB / 32; ++i) { a += wdd[i]; b += wpi[i]; }
        double s_dd = a / ((double)BATCHN * (double)NX);
        double s_pi = b / ((double)BATCHN * (double)NTOT);
        atomicAdd(&out[0], (float)(s_dd + 0.1 * s_pi));   // total_loss
        atomicAdd(&out[1], (float)s_dd);                  // l_dd
        atomicAdd(&out[2], (float)s_pi);                  // l_pi
    }
}

extern "C" void kernel_launch(void* const* d_in, const int* in_sizes, int n_in,
                              void* d_out, int out_size)
{
    const float* pred = (const float*)d_in[0];   // predictions [524288, 40]
    const float* targ = (const float*)d_in[1];   // targets     [524288, 40]
    const float* ycur = (const float*)d_in[2];   // y_current   [524288, 40]
    float* out = (float*)d_out;                  // [total, l_dd, l_pi]

    // Zero the (poisoned) output each invocation; capturable memset node.
    cudaMemsetAsync(d_out, 0, (size_t)out_size * sizeof(float), 0);
    hybrid_loss_kernel<<<GRID, TPB>>>(pred, targ, ycur, out);
}

// round 17
// speedup vs baseline: 1.2852x; 1.0046x over previous
#include <cuda_runtime.h>

#define NTOT      40
#define NX        20
#define BATCHN    524288
#define TPB       320
#define WPB       (TPB / 32)          // 10 warps per block
#define GRID      1480                // 148 SMs x 10 CTAs
#define NWARP     (GRID * WPB)        // 14800 warps; 3 rows per warp-iteration

__global__ __launch_bounds__(TPB) void hybrid_loss_kernel(
    const float* __restrict__ pred,
    const float* __restrict__ targ,
    const float* __restrict__ ycur,
    float* __restrict__ out)
{
    const int t    = threadIdx.x;
    const int lane = t & 31;
    const int wid  = t >> 5;
    const int j    = lane % 10;        // chunk within row (cols 4j..4j+3)
    const bool lane_ok = lane < 30;    // 3 rows x 10 chunks; lanes 30,31 idle
    const int rl   = lane_ok ? (lane / 10) : 0;   // row within warp triple

    const float4* __restrict__ p4 = (const float4*)pred;
    const float4* __restrict__ y4 = (const float4*)ycur;
    const float4* __restrict__ t4 = (const float4*)targ;

    const int W = blockIdx.x * WPB + wid;   // global warp id

    // Shuffle source lanes for the periodic stencil (same row, adjacent chunk).
    // x_{4j-2}, x_{4j-1} live in chunk j-1 (.z,.w); x_{4j+4} in chunk j+1 (.x);
    // wrap: chunk 0 <- chunk 9, chunk 9 -> chunk 0.
    const int dn = ((j == 0) ? lane + 9 : lane - 1) & 31;
    const int up = ((j == 9) ? lane - 9 : lane + 1) & 31;

    float acc_dd = 0.0f;
    float acc_pi = 0.0f;

    // ---- prefetch first warp-tile (3 rows, fully coalesced: idx = b*10 + lane) ----
    int b = W * 3;                                 // first row of this warp's triple
    int row = b + rl;
    bool pvalid = lane_ok && (row < BATCHN);
    int rowc = pvalid ? row : b;                   // clamp to an in-warp line: no extra traffic
    float4 pv = p4[rowc * 10 + j];
    float4 yv = y4[rowc * 10 + j];
    float4 tv = make_float4(0.f, 0.f, 0.f, 0.f);
    if (j < 5) tv = t4[rowc * 10 + j];             // observed cols 0..19 = chunks 0..4

    // Warps are fully independent: no smem, no barriers in the loop.
    for (; b < BATCHN; b += NWARP * 3) {
        float4 pc = pv;
        float4 yc = yv;
        float4 tc = tv;
        const bool cvalid = pvalid;

        // Prefetch next strided triple (uniform branch per warp).
        const int b2 = b + NWARP * 3;
        if (b2 < BATCHN) {
            int row2 = b2 + rl;
            pvalid = lane_ok && (row2 < BATCHN);
            int rowc2 = pvalid ? row2 : b2;
            pv = p4[rowc2 * 10 + j];
            yv = y4[rowc2 * 10 + j];
            if (j < 5) tv = t4[rowc2 * 10 + j];
        }

        // ---- neighbor exchange via warp shuffle (replaces smem + 2 barriers) ----
        const float xm2 = __shfl_sync(0xFFFFFFFFu, pc.z, dn);   // x_{4j-2}
        const float xm1 = __shfl_sync(0xFFFFFFFFu, pc.w, dn);   // x_{4j-1}
        const float xp4 = __shfl_sync(0xFFFFFFFFu, pc.x, up);   // x_{4j+4}

        // ---- physics term: Lorenz-96 RHS, all in registers ----
        {
            const float p0 = pc.x, p1 = pc.y, p2 = pc.z, p3 = pc.w;

            float f0 = (p1  - xm2) * xm1 - p0 + 8.0f;
            float f1 = (p2  - xm1) * p0  - p1 + 8.0f;
            float f2 = (p3  - p0 ) * p1  - p2 + 8.0f;
            float f3 = (xp4 - p1 ) * p2  - p3 + 8.0f;

            float d0 = (p0 - yc.x) * 100.0f - f0;
            float d1 = (p1 - yc.y) * 100.0f - f1;
            float d2 = (p2 - yc.z) * 100.0f - f2;
            float d3 = (p3 - yc.w) * 100.0f - f3;

            float s = d0 * d0 + d1 * d1 + d2 * d2 + d3 * d3;
            if (cvalid) acc_pi += s;
        }

        // ---- data-driven term: chunks 0..4 own observed cols in registers ----
        if (cvalid && j < 5) {
            float e0 = pc.x - tc.x;
            float e1 = pc.y - tc.y;
            float e2 = pc.z - tc.z;
            float e3 = pc.w - tc.w;
            acc_dd += e0 * e0 + e1 * e1 + e2 * e2 + e3 * e3;
        }
    }

    // ---- block reduction: warp shuffle (float) -> smem (double) ----
    #pragma unroll
    for (int o = 16; o; o >>= 1) {
        acc_dd += __shfl_xor_sync(0xFFFFFFFFu, acc_dd, o);
        acc_pi += __shfl_xor_sync(0xFFFFFFFFu, acc_pi, o);
    }
    __shared__ double wdd[WPB], wpi[WPB];
    if (lane == 0) { wdd[wid] = (double)acc_dd; wpi[wid] = (double)acc_pi; }
    __syncthreads();

    // ---- fire-and-forget: 3 scaled RED.ADD.F32 into d_out (proven R15 tail) ----
    if (t == 0) {
        double a = 0.0, bb = 0.0;
        #pragma unroll
        for (int i = 0; i < WPB; ++i) { a += wdd[i]; bb += wpi[i]; }
        double s_dd = a  / ((double)BATCHN * (double)NX);
        double s_pi = bb / ((double)BATCHN * (double)NTOT);
        atomicAdd(&out[0], (float)(s_dd + 0.1 * s_pi));   // total_loss
        atomicAdd(&out[1], (float)s_dd);                  // l_dd
        atomicAdd(&out[2], (float)s_pi);                  // l_pi
    }
}

extern "C" void kernel_launch(void* const* d_in, const int* in_sizes, int n_in,
                              void* d_out, int out_size)
{
    const float* pred = (const float*)d_in[0];   // predictions [524288, 40]
    const float* targ = (const float*)d_in[1];   // targets     [524288, 40]
    const float* ycur = (const float*)d_in[2];   // y_current   [524288, 40]
    float* out = (float*)d_out;                  // [total, l_dd, l_pi]

    // Zero the (poisoned) output each invocation; capturable memset node.
    cudaMemsetAsync(d_out, 0, (size_t)out_size * sizeof(float), 0);
    hybrid_loss_kernel<<<GRID, TPB>>>(pred, targ, ycur, out);
}